// round 5
// baseline (speedup 1.0000x reference)
#include <cuda_runtime.h>
#include <math.h>

#define NPTS 64     // NUM_POINTS
#define NCF  32     // NUM_COEFF
#define NB   30     // NUM_COEFF - 2
#define NITER 20
#define NPROB (256*512)
#define HALFP (NPROB/2)
#define PI_D 3.14159265358979323846

// ------------------------ device scratch (double, setup only) ---------------
__device__ double scr_T[NCF][NPTS];
__device__ double scr_DT[NCF][NPTS];
__device__ double scr_Gb[NB][NPTS];
__device__ double scr_M[NB][2*NB];
__device__ double scr_Cd[NPTS][NB];
__device__ double scr_tch[NPTS];
__device__ double scr_Dt[NPTS];
__device__ double scr_P0[NB], scr_P1[NB];

// ------------------------ constants for the main kernel (float) -------------
__device__ float c_G[NPTS][NCF];    // G[k][m] = T[m+2](tch_k) - P0[m] - P1[m]*tch_k ; pad m=30,31 -> 0
__device__ float c_C[NPTS][NCF];    // C[k][m] ; pad -> 0
__device__ float c_V[NCF];          // v[m] = sum_k C[k][m]
__device__ float c_P0[NCF], c_P1[NCF];
__device__ float c_tc1[NPTS];       // 1 + tch[k]
__device__ float c_sin[NPTS];       // sin(t_true[k])
__device__ float c_PO[NCF][16];     // Phi_out[c][t]
__device__ float c_scal[2];         // inv_s = (t1-t0)/2 , sin(t0)

// ==================== setup kernel: 1 block, 256 threads, fp64 ==============
__global__ void setup_kernel(const float* __restrict__ tspan) {
    int tid = threadIdx.x;
    double t0 = (double)tspan[0];
    double t1 = (double)tspan[15];
    double inv_s = 0.5 * (t1 - t0);
    __shared__ int s_piv;
    __shared__ double s_fac[NB];

    if (tid < NPTS) {
        scr_tch[tid] = -cos(PI_D * (double)tid / (double)NPTS);
    }
    __syncthreads();
    if (tid < NPTS) {
        double tnext = (tid == NPTS-1) ? 1.0 : scr_tch[tid+1];
        scr_Dt[tid]  = tnext - scr_tch[tid];
        double t = scr_tch[tid];
        double Tm2 = 1.0, Tm1 = t;
        scr_T[0][tid] = 1.0; scr_T[1][tid] = t;
        #pragma unroll 1
        for (int n = 2; n < NCF; n++) {
            double Tn = 2.0*t*Tm1 - Tm2; scr_T[n][tid] = Tn; Tm2 = Tm1; Tm1 = Tn;
        }
        double Ua = 1.0, Ub = 2.0*t;
        scr_DT[0][tid] = 0.0;
        scr_DT[1][tid] = 1.0;
        scr_DT[2][tid] = 2.0*Ub;
        #pragma unroll 1
        for (int n = 3; n < NCF; n++) {
            double Uc = 2.0*t*Ub - Ua;
            scr_DT[n][tid] = (double)n * Uc;
            Ua = Ub; Ub = Uc;
        }
    }
    __syncthreads();

    if (tid < NB) {
        double d0 = scr_DT[tid+2][0];
        scr_P1[tid] = d0;
        scr_P0[tid] = scr_T[tid+2][0] + d0;
    }
    __syncthreads();

    for (int e = tid; e < NB*NPTS; e += blockDim.x) {
        int m = e / NPTS, k = e % NPTS;
        scr_Gb[m][k] = scr_DT[m+2][k] - scr_P1[m];
    }
    __syncthreads();

    for (int e = tid; e < NB*NB; e += blockDim.x) {
        int i = e / NB, j = e % NB;
        double s = 0.0;
        for (int k = 0; k < NPTS; k++) s += scr_Gb[i][k]*scr_Dt[k]*scr_Gb[j][k];
        scr_M[i][j] = s;
        scr_M[i][NB+j] = (i == j) ? 1.0 : 0.0;
    }
    __syncthreads();

    for (int col = 0; col < NB; col++) {
        if (tid == 0) {
            int p = col; double best = fabs(scr_M[col][col]);
            for (int r = col+1; r < NB; r++) {
                double v = fabs(scr_M[r][col]);
                if (v > best) { best = v; p = r; }
            }
            s_piv = p;
        }
        __syncthreads();
        int p = s_piv;
        if (p != col && tid < 2*NB) {
            double tmp = scr_M[col][tid]; scr_M[col][tid] = scr_M[p][tid]; scr_M[p][tid] = tmp;
        }
        __syncthreads();
        double piv = scr_M[col][col];
        __syncthreads();
        if (tid < 2*NB) scr_M[col][tid] = scr_M[col][tid] / piv;
        if (tid < NB)   s_fac[tid] = scr_M[tid][col];
        __syncthreads();
        for (int e = tid; e < NB*2*NB; e += blockDim.x) {
            int r = e / (2*NB), c = e % (2*NB);
            if (r != col) scr_M[r][c] -= s_fac[r] * scr_M[col][c];
        }
        __syncthreads();
    }

    for (int e = tid; e < NPTS*NB; e += blockDim.x) {
        int k = e / NB, m = e % NB;
        double s = 0.0;
        for (int j = 0; j < NB; j++) s += scr_Gb[j][k] * scr_M[j][NB+m];
        scr_Cd[k][m] = scr_Dt[k] * s;
    }
    __syncthreads();

    for (int e = tid; e < NPTS*NCF; e += blockDim.x) {
        int k = e / NCF, m = e % NCF;
        float g = 0.f, cc = 0.f;
        if (m < NB) {
            g  = (float)(scr_T[m+2][k] - scr_P0[m] - scr_P1[m]*scr_tch[k]);
            cc = (float)scr_Cd[k][m];
        }
        c_G[k][m] = g;
        c_C[k][m] = cc;
    }
    if (tid < NCF) {
        double v = 0.0, p0 = 0.0, p1 = 0.0;
        if (tid < NB) {
            for (int k = 0; k < NPTS; k++) v += scr_Cd[k][tid];
            p0 = scr_P0[tid]; p1 = scr_P1[tid];
        }
        c_V[tid] = (float)v; c_P0[tid] = (float)p0; c_P1[tid] = (float)p1;
    }
    if (tid < NPTS) {
        c_tc1[tid] = (float)(1.0 + scr_tch[tid]);
        c_sin[tid] = (float)sin(t0 + inv_s * (scr_tch[tid] + 1.0));
    }
    if (tid == 0) { c_scal[0] = (float)inv_s; c_scal[1] = (float)sin(t0); }
    if (tid < 16) {
        double tq = -1.0 + 2.0*((double)tspan[tid] - t0)/(t1 - t0);
        double Tm2 = 1.0, Tm1 = tq;
        c_PO[0][tid] = 1.0f; c_PO[1][tid] = (float)tq;
        #pragma unroll 1
        for (int n = 2; n < NCF; n++) {
            double Tn = 2.0*tq*Tm1 - Tm2; c_PO[n][tid] = (float)Tn; Tm2 = Tm1; Tm1 = Tn;
        }
    }
}

// ==================== packed f32x2 helpers ==================================
typedef unsigned long long u64;

__device__ __forceinline__ u64 pk2(float lo, float hi) {
    u64 r; asm("mov.b64 %0, {%1, %2};" : "=l"(r) : "f"(lo), "f"(hi)); return r;
}
__device__ __forceinline__ void upk2(u64 v, float& lo, float& hi) {
    asm("mov.b64 {%0, %1}, %2;" : "=f"(lo), "=f"(hi) : "l"(v));
}
__device__ __forceinline__ u64 fma2(u64 a, u64 b, u64 c) {
    u64 d; asm("fma.rn.f32x2 %0, %1, %2, %3;" : "=l"(d) : "l"(a), "l"(b), "l"(c)); return d;
}
__device__ __forceinline__ u64 mul2(u64 a, u64 b) {
    u64 d; asm("mul.rn.f32x2 %0, %1, %2;" : "=l"(d) : "l"(a), "l"(b)); return d;
}

__device__ __forceinline__ float fast_tanh(float x) {
    float ax = fabsf(x);
    float e  = __expf(-2.0f * ax);                 // MUFU.EX2 path
    float t  = __fdividef(1.0f - e, 1.0f + e);     // MUFU.RCP path
    return copysignf(t, x);
}

// ==================== main solve kernel =====================================
// 2 problems per thread (idx and idx+HALFP); B/acc held as f32x2 coefficient
// pairs; G/C read from shared as ulonglong2 (LDS.128 = 2 packed pairs).
__global__ void __launch_bounds__(128, 3) solve_kernel(
    const float* __restrict__ y_init, const float* __restrict__ Bin,
    const float* __restrict__ a, float* __restrict__ out)
{
    __shared__ float sG[NPTS][NCF];
    __shared__ float sC[NPTS][NCF];
    __shared__ float sTc1[NPTS], sSin[NPTS];
    __shared__ float sV[NCF], sP0[NCF], sP1[NCF];
    __shared__ float sPO[NCF][16];
    __shared__ float sScal[2];

    int tid = threadIdx.x;
    for (int e = tid; e < NPTS*NCF; e += 128) {
        (&sG[0][0])[e] = (&c_G[0][0])[e];
        (&sC[0][0])[e] = (&c_C[0][0])[e];
    }
    if (tid < NPTS) { sTc1[tid] = c_tc1[tid]; sSin[tid] = c_sin[tid]; }
    if (tid < NCF)  { sV[tid] = c_V[tid]; sP0[tid] = c_P0[tid]; sP1[tid] = c_P1[tid]; }
    for (int e = tid; e < NCF*16; e += 128) (&sPO[0][0])[e] = (&c_PO[0][0])[e];
    if (tid < 2) sScal[tid] = c_scal[tid];
    __syncthreads();

    int idxA = blockIdx.x * 128 + tid;
    int idxB = idxA + HALFP;
    float invs = sScal[0];
    float sin0 = sScal[1];

    float yA = y_init[idxA], yB = y_init[idxB];
    float ajA = a[idxA & 511], ajB = a[idxB & 511];
    float wA = (sin0 - fast_tanh(yA * ajA)) * invs;
    float wB = (sin0 - fast_tanh(yB * ajB)) * invs;

    // B coefficients as 16 packed pairs per problem (pair 15 = (B30,B31) = 0 pad)
    u64 BA[16], BB[16];
    {
        const float* ba = Bin + (long)idxA * NB;
        const float* bb = Bin + (long)idxB * NB;
        #pragma unroll
        for (int i = 0; i < 15; i++) {
            BA[i] = pk2(ba[2*i], ba[2*i+1]);
            BB[i] = pk2(bb[2*i], bb[2*i+1]);
        }
        BA[15] = pk2(0.f, 0.f);
        BB[15] = pk2(0.f, 0.f);
    }
    u64 invs2 = pk2(invs, invs);
    u64 nwA2  = pk2(-wA, -wA);
    u64 nwB2  = pk2(-wB, -wB);

    #pragma unroll 1
    for (int it = 0; it < NITER; it++) {
        u64 accA[16], accB[16];
        #pragma unroll
        for (int i = 0; i < 16; i++) { accA[i] = 0ull; accB[i] = 0ull; }

        #pragma unroll 2
        for (int k = 0; k < NPTS; k++) {
            float tc1 = sTc1[k];
            // two partial chains per problem for ILP
            u64 pa0 = pk2(fmaf(wA, tc1, yA), 0.f);
            u64 pa1 = 0ull;
            u64 pb0 = pk2(fmaf(wB, tc1, yB), 0.f);
            u64 pb1 = 0ull;
            const ulonglong2* g2 = (const ulonglong2*)&sG[k][0];   // 8 x LDS.128
            #pragma unroll
            for (int q = 0; q < 8; q++) {
                ulonglong2 g = g2[q];
                pa0 = fma2(BA[2*q],   g.x, pa0);
                pa1 = fma2(BA[2*q+1], g.y, pa1);
                pb0 = fma2(BB[2*q],   g.x, pb0);
                pb1 = fma2(BB[2*q+1], g.y, pb1);
            }
            float a0,a1,a2,a3, b0,b1,b2,b3;
            upk2(pa0, a0, a1); upk2(pa1, a2, a3);
            upk2(pb0, b0, b1); upk2(pb1, b2, b3);
            float yaA = (a0 + a1) + (a2 + a3);
            float yaB = (b0 + b1) + (b2 + b3);
            float sk = sSin[k];
            float fA = sk - fast_tanh(yaA * ajA);
            float fB = sk - fast_tanh(yaB * ajB);
            u64 fA2 = pk2(fA, fA);
            u64 fB2 = pk2(fB, fB);
            const ulonglong2* c2 = (const ulonglong2*)&sC[k][0];   // 8 x LDS.128
            #pragma unroll
            for (int q = 0; q < 8; q++) {
                ulonglong2 c = c2[q];
                accA[2*q]   = fma2(fA2, c.x, accA[2*q]);
                accA[2*q+1] = fma2(fA2, c.y, accA[2*q+1]);
                accB[2*q]   = fma2(fB2, c.x, accB[2*q]);
                accB[2*q+1] = fma2(fB2, c.y, accB[2*q+1]);
            }
        }

        // B = invs*acc - w*V   (V pairs from shared; pad pair stays 0)
        const ulonglong2* v2 = (const ulonglong2*)&sV[0];
        #pragma unroll
        for (int q = 0; q < 8; q++) {
            ulonglong2 v = v2[q];
            BA[2*q]   = fma2(invs2, accA[2*q],   mul2(nwA2, v.x));
            BA[2*q+1] = fma2(invs2, accA[2*q+1], mul2(nwA2, v.y));
            BB[2*q]   = fma2(invs2, accB[2*q],   mul2(nwB2, v.x));
            BB[2*q+1] = fma2(invs2, accB[2*q+1], mul2(nwB2, v.y));
        }
    }

    // unpack B back to scalars
    float Bs_A[NCF], Bs_B[NCF];
    #pragma unroll
    for (int i = 0; i < 16; i++) {
        upk2(BA[i], Bs_A[2*i], Bs_A[2*i+1]);
        upk2(BB[i], Bs_B[2*i], Bs_B[2*i+1]);
    }

    // head = yf@inv0 - B@P
    float h0A = yA + wA, h1A = wA;
    float h0B = yB + wB, h1B = wB;
    #pragma unroll
    for (int m = 0; m < NB; m++) {
        float p0 = sP0[m], p1 = sP1[m];
        h0A = fmaf(-Bs_A[m], p0, h0A);
        h1A = fmaf(-Bs_A[m], p1, h1A);
        h0B = fmaf(-Bs_B[m], p0, h0B);
        h1B = fmaf(-Bs_B[m], p1, h1B);
    }

    // B_full: (256,512,32) after the approx block
    float* outB = out + 16*NPROB;
    {
        long ba = (long)idxA * NCF;
        long bb = (long)idxB * NCF;
        outB[ba]   = h0A; outB[ba+1] = h1A;
        outB[bb]   = h0B; outB[bb+1] = h1B;
        #pragma unroll
        for (int m = 0; m < NB; m++) {
            outB[ba+2+m] = Bs_A[m];
            outB[bb+2+m] = Bs_B[m];
        }
    }

    // approx: (16,256,512), coalesced over idx
    #pragma unroll
    for (int t = 0; t < 16; t++) {
        float vA = fmaf(h0A, sPO[0][t], h1A * sPO[1][t]);
        float vB = fmaf(h0B, sPO[0][t], h1B * sPO[1][t]);
        #pragma unroll
        for (int m = 0; m < NB; m++) {
            float po = sPO[m+2][t];
            vA = fmaf(Bs_A[m], po, vA);
            vB = fmaf(Bs_B[m], po, vB);
        }
        out[t*NPROB + idxA] = vA;
        out[t*NPROB + idxB] = vB;
    }
}

// ==================== launch ================================================
extern "C" void kernel_launch(void* const* d_in, const int* in_sizes, int n_in,
                              void* d_out, int out_size) {
    const float* y_init = (const float*)d_in[0];
    const float* B_init = (const float*)d_in[1];
    const float* t_span = (const float*)d_in[2];
    const float* a      = (const float*)d_in[3];
    float* out = (float*)d_out;
    setup_kernel<<<1, 256>>>(t_span);
    solve_kernel<<<HALFP/128, 128>>>(y_init, B_init, a, out);
}

// round 6
// speedup vs baseline: 1.0051x; 1.0051x over previous
#include <cuda_runtime.h>
#include <math.h>

#define NPTS 64     // NUM_POINTS
#define NCF  32     // NUM_COEFF
#define NB   30     // NUM_COEFF - 2
#define NITER 20
#define NPROB (256*512)
#define HALFP (NPROB/2)
#define PI_D 3.14159265358979323846

// ------------------------ device scratch (double, setup only) ---------------
__device__ double scr_T[NCF][NPTS];
__device__ double scr_DT[NCF][NPTS];
__device__ double scr_Gb[NB][NPTS];
__device__ double scr_M[NB][2*NB];
__device__ double scr_Cd[NPTS][NB];
__device__ double scr_tch[NPTS];
__device__ double scr_Dt[NPTS];
__device__ double scr_P0[NB], scr_P1[NB];

// ------------------------ constants for the main kernel (float) -------------
__device__ float c_G[NPTS][NCF];    // G[k][m] = T[m+2](tch_k) - P0[m] - P1[m]*tch_k ; pad m=30,31 -> 0
__device__ float c_C[NPTS][NCF];    // C[k][m] ; pad -> 0
__device__ float c_V[NCF];          // v[m] = sum_k C[k][m]
__device__ float c_P0[NCF], c_P1[NCF];
__device__ float c_tc1[NPTS];       // 1 + tch[k]
__device__ float c_sin[NPTS];       // sin(t_true[k])
__device__ float c_PO[NCF][16];     // Phi_out[c][t]
__device__ float c_scal[2];         // inv_s = (t1-t0)/2 , sin(t0)

// ==================== setup kernel: 1 block, 256 threads, fp64 ==============
__global__ void setup_kernel(const float* __restrict__ tspan) {
    int tid = threadIdx.x;
    double t0 = (double)tspan[0];
    double t1 = (double)tspan[15];
    double inv_s = 0.5 * (t1 - t0);
    __shared__ int s_piv;
    __shared__ double s_fac[NB];

    if (tid < NPTS) {
        scr_tch[tid] = -cos(PI_D * (double)tid / (double)NPTS);
    }
    __syncthreads();
    if (tid < NPTS) {
        double tnext = (tid == NPTS-1) ? 1.0 : scr_tch[tid+1];
        scr_Dt[tid]  = tnext - scr_tch[tid];
        double t = scr_tch[tid];
        double Tm2 = 1.0, Tm1 = t;
        scr_T[0][tid] = 1.0; scr_T[1][tid] = t;
        #pragma unroll 1
        for (int n = 2; n < NCF; n++) {
            double Tn = 2.0*t*Tm1 - Tm2; scr_T[n][tid] = Tn; Tm2 = Tm1; Tm1 = Tn;
        }
        double Ua = 1.0, Ub = 2.0*t;
        scr_DT[0][tid] = 0.0;
        scr_DT[1][tid] = 1.0;
        scr_DT[2][tid] = 2.0*Ub;
        #pragma unroll 1
        for (int n = 3; n < NCF; n++) {
            double Uc = 2.0*t*Ub - Ua;
            scr_DT[n][tid] = (double)n * Uc;
            Ua = Ub; Ub = Uc;
        }
    }
    __syncthreads();

    if (tid < NB) {
        double d0 = scr_DT[tid+2][0];
        scr_P1[tid] = d0;
        scr_P0[tid] = scr_T[tid+2][0] + d0;
    }
    __syncthreads();

    for (int e = tid; e < NB*NPTS; e += blockDim.x) {
        int m = e / NPTS, k = e % NPTS;
        scr_Gb[m][k] = scr_DT[m+2][k] - scr_P1[m];
    }
    __syncthreads();

    for (int e = tid; e < NB*NB; e += blockDim.x) {
        int i = e / NB, j = e % NB;
        double s = 0.0;
        for (int k = 0; k < NPTS; k++) s += scr_Gb[i][k]*scr_Dt[k]*scr_Gb[j][k];
        scr_M[i][j] = s;
        scr_M[i][NB+j] = (i == j) ? 1.0 : 0.0;
    }
    __syncthreads();

    for (int col = 0; col < NB; col++) {
        if (tid == 0) {
            int p = col; double best = fabs(scr_M[col][col]);
            for (int r = col+1; r < NB; r++) {
                double v = fabs(scr_M[r][col]);
                if (v > best) { best = v; p = r; }
            }
            s_piv = p;
        }
        __syncthreads();
        int p = s_piv;
        if (p != col && tid < 2*NB) {
            double tmp = scr_M[col][tid]; scr_M[col][tid] = scr_M[p][tid]; scr_M[p][tid] = tmp;
        }
        __syncthreads();
        double piv = scr_M[col][col];
        __syncthreads();
        if (tid < 2*NB) scr_M[col][tid] = scr_M[col][tid] / piv;
        if (tid < NB)   s_fac[tid] = scr_M[tid][col];
        __syncthreads();
        for (int e = tid; e < NB*2*NB; e += blockDim.x) {
            int r = e / (2*NB), c = e % (2*NB);
            if (r != col) scr_M[r][c] -= s_fac[r] * scr_M[col][c];
        }
        __syncthreads();
    }

    for (int e = tid; e < NPTS*NB; e += blockDim.x) {
        int k = e / NB, m = e % NB;
        double s = 0.0;
        for (int j = 0; j < NB; j++) s += scr_Gb[j][k] * scr_M[j][NB+m];
        scr_Cd[k][m] = scr_Dt[k] * s;
    }
    __syncthreads();

    for (int e = tid; e < NPTS*NCF; e += blockDim.x) {
        int k = e / NCF, m = e % NCF;
        float g = 0.f, cc = 0.f;
        if (m < NB) {
            g  = (float)(scr_T[m+2][k] - scr_P0[m] - scr_P1[m]*scr_tch[k]);
            cc = (float)scr_Cd[k][m];
        }
        c_G[k][m] = g;
        c_C[k][m] = cc;
    }
    if (tid < NCF) {
        double v = 0.0, p0 = 0.0, p1 = 0.0;
        if (tid < NB) {
            for (int k = 0; k < NPTS; k++) v += scr_Cd[k][tid];
            p0 = scr_P0[tid]; p1 = scr_P1[tid];
        }
        c_V[tid] = (float)v; c_P0[tid] = (float)p0; c_P1[tid] = (float)p1;
    }
    if (tid < NPTS) {
        c_tc1[tid] = (float)(1.0 + scr_tch[tid]);
        c_sin[tid] = (float)sin(t0 + inv_s * (scr_tch[tid] + 1.0));
    }
    if (tid == 0) { c_scal[0] = (float)inv_s; c_scal[1] = (float)sin(t0); }
    if (tid < 16) {
        double tq = -1.0 + 2.0*((double)tspan[tid] - t0)/(t1 - t0);
        double Tm2 = 1.0, Tm1 = tq;
        c_PO[0][tid] = 1.0f; c_PO[1][tid] = (float)tq;
        #pragma unroll 1
        for (int n = 2; n < NCF; n++) {
            double Tn = 2.0*tq*Tm1 - Tm2; c_PO[n][tid] = (float)Tn; Tm2 = Tm1; Tm1 = Tn;
        }
    }
}

// ==================== packed f32x2 helpers ==================================
typedef unsigned long long u64;

__device__ __forceinline__ u64 pk2(float lo, float hi) {
    u64 r; asm("mov.b64 %0, {%1, %2};" : "=l"(r) : "f"(lo), "f"(hi)); return r;
}
__device__ __forceinline__ void upk2(u64 v, float& lo, float& hi) {
    asm("mov.b64 {%0, %1}, %2;" : "=f"(lo), "=f"(hi) : "l"(v));
}
__device__ __forceinline__ u64 fma2(u64 a, u64 b, u64 c) {
    u64 d; asm("fma.rn.f32x2 %0, %1, %2, %3;" : "=l"(d) : "l"(a), "l"(b), "l"(c)); return d;
}
__device__ __forceinline__ u64 mul2(u64 a, u64 b) {
    u64 d; asm("mul.rn.f32x2 %0, %1, %2;" : "=l"(d) : "l"(a), "l"(b)); return d;
}

__device__ __forceinline__ float fast_tanh(float x) {
    float ax = fabsf(x);
    float e  = __expf(-2.0f * ax);                 // MUFU.EX2 path
    float t  = __fdividef(1.0f - e, 1.0f + e);     // MUFU.RCP path
    return copysignf(t, x);
}

// ==================== main solve kernel =====================================
// 2 problems per thread (idx and idx+HALFP); B/acc held as f32x2 coefficient
// pairs; G/C read from shared as ulonglong2 (LDS.128 = 2 packed pairs).
__global__ void __launch_bounds__(128, 3) solve_kernel(
    const float* __restrict__ y_init, const float* __restrict__ Bin,
    const float* __restrict__ a, float* __restrict__ out)
{
    __shared__ float sG[NPTS][NCF];
    __shared__ float sC[NPTS][NCF];
    __shared__ float sTc1[NPTS], sSin[NPTS];
    __shared__ float sV[NCF], sP0[NCF], sP1[NCF];
    __shared__ float sPO[NCF][16];
    __shared__ float sScal[2];

    int tid = threadIdx.x;
    for (int e = tid; e < NPTS*NCF; e += 128) {
        (&sG[0][0])[e] = (&c_G[0][0])[e];
        (&sC[0][0])[e] = (&c_C[0][0])[e];
    }
    if (tid < NPTS) { sTc1[tid] = c_tc1[tid]; sSin[tid] = c_sin[tid]; }
    if (tid < NCF)  { sV[tid] = c_V[tid]; sP0[tid] = c_P0[tid]; sP1[tid] = c_P1[tid]; }
    for (int e = tid; e < NCF*16; e += 128) (&sPO[0][0])[e] = (&c_PO[0][0])[e];
    if (tid < 2) sScal[tid] = c_scal[tid];
    __syncthreads();

    int idxA = blockIdx.x * 128 + tid;
    int idxB = idxA + HALFP;
    float invs = sScal[0];
    float sin0 = sScal[1];

    float yA = y_init[idxA], yB = y_init[idxB];
    float ajA = a[idxA & 511], ajB = a[idxB & 511];
    float wA = (sin0 - fast_tanh(yA * ajA)) * invs;
    float wB = (sin0 - fast_tanh(yB * ajB)) * invs;

    // B coefficients as 16 packed pairs per problem (pair 15 = (B30,B31) = 0 pad)
    u64 BA[16], BB[16];
    {
        const float* ba = Bin + (long)idxA * NB;
        const float* bb = Bin + (long)idxB * NB;
        #pragma unroll
        for (int i = 0; i < 15; i++) {
            BA[i] = pk2(ba[2*i], ba[2*i+1]);
            BB[i] = pk2(bb[2*i], bb[2*i+1]);
        }
        BA[15] = pk2(0.f, 0.f);
        BB[15] = pk2(0.f, 0.f);
    }
    u64 invs2 = pk2(invs, invs);
    u64 nwA2  = pk2(-wA, -wA);
    u64 nwB2  = pk2(-wB, -wB);

    #pragma unroll 1
    for (int it = 0; it < NITER; it++) {
        u64 accA[16], accB[16];
        #pragma unroll
        for (int i = 0; i < 16; i++) { accA[i] = 0ull; accB[i] = 0ull; }

        #pragma unroll 2
        for (int k = 0; k < NPTS; k++) {
            float tc1 = sTc1[k];
            // two partial chains per problem for ILP
            u64 pa0 = pk2(fmaf(wA, tc1, yA), 0.f);
            u64 pa1 = 0ull;
            u64 pb0 = pk2(fmaf(wB, tc1, yB), 0.f);
            u64 pb1 = 0ull;
            const ulonglong2* g2 = (const ulonglong2*)&sG[k][0];   // 8 x LDS.128
            #pragma unroll
            for (int q = 0; q < 8; q++) {
                ulonglong2 g = g2[q];
                pa0 = fma2(BA[2*q],   g.x, pa0);
                pa1 = fma2(BA[2*q+1], g.y, pa1);
                pb0 = fma2(BB[2*q],   g.x, pb0);
                pb1 = fma2(BB[2*q+1], g.y, pb1);
            }
            float a0,a1,a2,a3, b0,b1,b2,b3;
            upk2(pa0, a0, a1); upk2(pa1, a2, a3);
            upk2(pb0, b0, b1); upk2(pb1, b2, b3);
            float yaA = (a0 + a1) + (a2 + a3);
            float yaB = (b0 + b1) + (b2 + b3);
            float sk = sSin[k];
            float fA = sk - fast_tanh(yaA * ajA);
            float fB = sk - fast_tanh(yaB * ajB);
            u64 fA2 = pk2(fA, fA);
            u64 fB2 = pk2(fB, fB);
            const ulonglong2* c2 = (const ulonglong2*)&sC[k][0];   // 8 x LDS.128
            #pragma unroll
            for (int q = 0; q < 8; q++) {
                ulonglong2 c = c2[q];
                accA[2*q]   = fma2(fA2, c.x, accA[2*q]);
                accA[2*q+1] = fma2(fA2, c.y, accA[2*q+1]);
                accB[2*q]   = fma2(fB2, c.x, accB[2*q]);
                accB[2*q+1] = fma2(fB2, c.y, accB[2*q+1]);
            }
        }

        // B = invs*acc - w*V   (V pairs from shared; pad pair stays 0)
        const ulonglong2* v2 = (const ulonglong2*)&sV[0];
        #pragma unroll
        for (int q = 0; q < 8; q++) {
            ulonglong2 v = v2[q];
            BA[2*q]   = fma2(invs2, accA[2*q],   mul2(nwA2, v.x));
            BA[2*q+1] = fma2(invs2, accA[2*q+1], mul2(nwA2, v.y));
            BB[2*q]   = fma2(invs2, accB[2*q],   mul2(nwB2, v.x));
            BB[2*q+1] = fma2(invs2, accB[2*q+1], mul2(nwB2, v.y));
        }
    }

    // unpack B back to scalars
    float Bs_A[NCF], Bs_B[NCF];
    #pragma unroll
    for (int i = 0; i < 16; i++) {
        upk2(BA[i], Bs_A[2*i], Bs_A[2*i+1]);
        upk2(BB[i], Bs_B[2*i], Bs_B[2*i+1]);
    }

    // head = yf@inv0 - B@P
    float h0A = yA + wA, h1A = wA;
    float h0B = yB + wB, h1B = wB;
    #pragma unroll
    for (int m = 0; m < NB; m++) {
        float p0 = sP0[m], p1 = sP1[m];
        h0A = fmaf(-Bs_A[m], p0, h0A);
        h1A = fmaf(-Bs_A[m], p1, h1A);
        h0B = fmaf(-Bs_B[m], p0, h0B);
        h1B = fmaf(-Bs_B[m], p1, h1B);
    }

    // B_full: (256,512,32) after the approx block
    float* outB = out + 16*NPROB;
    {
        long ba = (long)idxA * NCF;
        long bb = (long)idxB * NCF;
        outB[ba]   = h0A; outB[ba+1] = h1A;
        outB[bb]   = h0B; outB[bb+1] = h1B;
        #pragma unroll
        for (int m = 0; m < NB; m++) {
            outB[ba+2+m] = Bs_A[m];
            outB[bb+2+m] = Bs_B[m];
        }
    }

    // approx: (16,256,512), coalesced over idx
    #pragma unroll
    for (int t = 0; t < 16; t++) {
        float vA = fmaf(h0A, sPO[0][t], h1A * sPO[1][t]);
        float vB = fmaf(h0B, sPO[0][t], h1B * sPO[1][t]);
        #pragma unroll
        for (int m = 0; m < NB; m++) {
            float po = sPO[m+2][t];
            vA = fmaf(Bs_A[m], po, vA);
            vB = fmaf(Bs_B[m], po, vB);
        }
        out[t*NPROB + idxA] = vA;
        out[t*NPROB + idxB] = vB;
    }
}

// ==================== launch ================================================
extern "C" void kernel_launch(void* const* d_in, const int* in_sizes, int n_in,
                              void* d_out, int out_size) {
    const float* y_init = (const float*)d_in[0];
    const float* B_init = (const float*)d_in[1];
    const float* t_span = (const float*)d_in[2];
    const float* a      = (const float*)d_in[3];
    float* out = (float*)d_out;
    setup_kernel<<<1, 256>>>(t_span);
    solve_kernel<<<HALFP/128, 128>>>(y_init, B_init, a, out);
}

// round 8
// speedup vs baseline: 2.0618x; 2.0512x over previous
#include <cuda_runtime.h>
#include <cuda_bf16.h>
#include <math.h>

#define NPTS 64
#define NCF  32
#define NB   30
#define NITER 20
#define NPROB (256*512)
#define PI_D 3.14159265358979323846

#define GS 17    // u32 words per row of packed G   (16 data + 1 pad)
#define CS 36    // u32 words per row of packed C^T (32 data + 4 pad)
#define BSS 40   // bf16 per column of B staging (32 + 8 pad)
#define FSS 72   // bf16 per column of F staging (64 + 8 pad)

// ------------------------ device scratch (double, setup only) ---------------
__device__ double scr_T[NCF][NPTS];
__device__ double scr_DT[NCF][NPTS];
__device__ double scr_Gb[NB][NPTS];
__device__ double scr_M[NB][2*NB];
__device__ double scr_Cd[NPTS][NB];
__device__ double scr_tch[NPTS];
__device__ double scr_Dt[NPTS];
__device__ double scr_P0[NB], scr_P1[NB];

// ------------------------ constants for solve kernel ------------------------
__device__ unsigned g_Ghi[64*GS], g_Glo[64*GS];   // packed bf16x2 of G (64 x 32)
__device__ unsigned g_Chi[32*CS], g_Clo[32*CS];   // packed bf16x2 of C^T (32 x 64)
__device__ float c_sin[NPTS], c_tc1[NPTS];
__device__ float c_V[NCF], c_P0[NCF], c_P1[NCF];
__device__ float c_PO[NCF][16];
__device__ float c_scal[2];          // inv_s, sin(t0)

// ==================== setup kernel: 1 block, 256 threads, fp64 ==============
__global__ void setup_kernel(const float* __restrict__ tspan) {
    int tid = threadIdx.x;
    double t0 = (double)tspan[0];
    double t1 = (double)tspan[15];
    double inv_s = 0.5 * (t1 - t0);
    __shared__ int s_piv;
    __shared__ double s_fac[NB];

    if (tid < NPTS) scr_tch[tid] = -cos(PI_D * (double)tid / (double)NPTS);
    __syncthreads();
    if (tid < NPTS) {
        double tnext = (tid == NPTS-1) ? 1.0 : scr_tch[tid+1];
        scr_Dt[tid]  = tnext - scr_tch[tid];
        double t = scr_tch[tid];
        double Tm2 = 1.0, Tm1 = t;
        scr_T[0][tid] = 1.0; scr_T[1][tid] = t;
        #pragma unroll 1
        for (int n = 2; n < NCF; n++) {
            double Tn = 2.0*t*Tm1 - Tm2; scr_T[n][tid] = Tn; Tm2 = Tm1; Tm1 = Tn;
        }
        double Ua = 1.0, Ub = 2.0*t;
        scr_DT[0][tid] = 0.0;
        scr_DT[1][tid] = 1.0;
        scr_DT[2][tid] = 2.0*Ub;
        #pragma unroll 1
        for (int n = 3; n < NCF; n++) {
            double Uc = 2.0*t*Ub - Ua;
            scr_DT[n][tid] = (double)n * Uc;
            Ua = Ub; Ub = Uc;
        }
    }
    __syncthreads();

    if (tid < NB) {
        double d0 = scr_DT[tid+2][0];
        scr_P1[tid] = d0;
        scr_P0[tid] = scr_T[tid+2][0] + d0;
    }
    __syncthreads();

    for (int e = tid; e < NB*NPTS; e += blockDim.x) {
        int m = e / NPTS, k = e % NPTS;
        scr_Gb[m][k] = scr_DT[m+2][k] - scr_P1[m];
    }
    __syncthreads();

    for (int e = tid; e < NB*NB; e += blockDim.x) {
        int i = e / NB, j = e % NB;
        double s = 0.0;
        for (int k = 0; k < NPTS; k++) s += scr_Gb[i][k]*scr_Dt[k]*scr_Gb[j][k];
        scr_M[i][j] = s;
        scr_M[i][NB+j] = (i == j) ? 1.0 : 0.0;
    }
    __syncthreads();

    for (int col = 0; col < NB; col++) {
        if (tid == 0) {
            int p = col; double best = fabs(scr_M[col][col]);
            for (int r = col+1; r < NB; r++) {
                double v = fabs(scr_M[r][col]);
                if (v > best) { best = v; p = r; }
            }
            s_piv = p;
        }
        __syncthreads();
        int p = s_piv;
        if (p != col && tid < 2*NB) {
            double tmp = scr_M[col][tid]; scr_M[col][tid] = scr_M[p][tid]; scr_M[p][tid] = tmp;
        }
        __syncthreads();
        double piv = scr_M[col][col];
        __syncthreads();
        if (tid < 2*NB) scr_M[col][tid] = scr_M[col][tid] / piv;
        if (tid < NB)   s_fac[tid] = scr_M[tid][col];
        __syncthreads();
        for (int e = tid; e < NB*2*NB; e += blockDim.x) {
            int r = e / (2*NB), c = e % (2*NB);
            if (r != col) scr_M[r][c] -= s_fac[r] * scr_M[col][c];
        }
        __syncthreads();
    }

    for (int e = tid; e < NPTS*NB; e += blockDim.x) {
        int k = e / NB, m = e % NB;
        double s = 0.0;
        for (int j = 0; j < NB; j++) s += scr_Gb[j][k] * scr_M[j][NB+m];
        scr_Cd[k][m] = scr_Dt[k] * s;
    }
    __syncthreads();

    // ---- pack G (64 pts x 32 coefs) as bf16x2 words, rn hi/lo split ----
    for (int e = tid; e < 64*16; e += blockDim.x) {
        int r = e >> 4, c = e & 15;
        float f0 = 0.f, f1 = 0.f;
        int m0 = 2*c, m1 = 2*c + 1;
        if (m0 < NB) f0 = (float)(scr_T[m0+2][r] - scr_P0[m0] - scr_P1[m0]*scr_tch[r]);
        if (m1 < NB) f1 = (float)(scr_T[m1+2][r] - scr_P0[m1] - scr_P1[m1]*scr_tch[r]);
        __nv_bfloat16 h0 = __float2bfloat16(f0), h1 = __float2bfloat16(f1);
        __nv_bfloat16 l0 = __float2bfloat16(f0 - __bfloat162float(h0));
        __nv_bfloat16 l1 = __float2bfloat16(f1 - __bfloat162float(h1));
        unsigned short b;
        unsigned wh, wl;
        memcpy(&b, &h0, 2); wh = b;
        memcpy(&b, &h1, 2); wh |= (unsigned)b << 16;
        memcpy(&b, &l0, 2); wl = b;
        memcpy(&b, &l1, 2); wl |= (unsigned)b << 16;
        g_Ghi[r*GS + c] = wh;
        g_Glo[r*GS + c] = wl;
    }
    // ---- pack C^T (32 coefs x 64 pts): CT[m][k] = Cd[k][m] ----
    for (int e = tid; e < 32*32; e += blockDim.x) {
        int m = e >> 5, c = e & 31;
        float f0 = 0.f, f1 = 0.f;
        if (m < NB) { f0 = (float)scr_Cd[2*c][m]; f1 = (float)scr_Cd[2*c+1][m]; }
        __nv_bfloat16 h0 = __float2bfloat16(f0), h1 = __float2bfloat16(f1);
        __nv_bfloat16 l0 = __float2bfloat16(f0 - __bfloat162float(h0));
        __nv_bfloat16 l1 = __float2bfloat16(f1 - __bfloat162float(h1));
        unsigned short b;
        unsigned wh, wl;
        memcpy(&b, &h0, 2); wh = b;
        memcpy(&b, &h1, 2); wh |= (unsigned)b << 16;
        memcpy(&b, &l0, 2); wl = b;
        memcpy(&b, &l1, 2); wl |= (unsigned)b << 16;
        g_Chi[m*CS + c] = wh;
        g_Clo[m*CS + c] = wl;
    }

    if (tid < NCF) {
        double v = 0.0, p0 = 0.0, p1 = 0.0;
        if (tid < NB) {
            for (int k = 0; k < NPTS; k++) v += scr_Cd[k][tid];
            p0 = scr_P0[tid]; p1 = scr_P1[tid];
        }
        c_V[tid] = (float)v; c_P0[tid] = (float)p0; c_P1[tid] = (float)p1;
    }
    if (tid < NPTS) {
        c_tc1[tid] = (float)(1.0 + scr_tch[tid]);
        c_sin[tid] = (float)sin(t0 + inv_s * (scr_tch[tid] + 1.0));
    }
    if (tid == 0) { c_scal[0] = (float)inv_s; c_scal[1] = (float)sin(t0); }
    if (tid < 16) {
        double tq = -1.0 + 2.0*((double)tspan[tid] - t0)/(t1 - t0);
        double Tm2 = 1.0, Tm1 = tq;
        c_PO[0][tid] = 1.0f; c_PO[1][tid] = (float)tq;
        #pragma unroll 1
        for (int n = 2; n < NCF; n++) {
            double Tn = 2.0*tq*Tm1 - Tm2; c_PO[n][tid] = (float)Tn; Tm2 = Tm1; Tm1 = Tn;
        }
    }
}

// ==================== solve kernel helpers ==================================
__device__ __forceinline__ float fast_tanh(float x) {
    float ax = fabsf(x);
    float e  = __expf(-2.0f * ax);
    float t  = __fdividef(1.0f - e, 1.0f + e);
    return copysignf(t, x);
}

__device__ __forceinline__ void mma_bf16(float* d,
    unsigned a0, unsigned a1, unsigned a2, unsigned a3,
    unsigned b0, unsigned b1)
{
    asm("mma.sync.aligned.m16n8k16.row.col.f32.bf16.bf16.f32 "
        "{%0,%1,%2,%3}, {%4,%5,%6,%7}, {%8,%9}, {%0,%1,%2,%3};"
        : "+f"(d[0]), "+f"(d[1]), "+f"(d[2]), "+f"(d[3])
        : "r"(a0), "r"(a1), "r"(a2), "r"(a3), "r"(b0), "r"(b1));
}

// truncation split: hi = f with low 16 bits zeroed, lo = rn(f - hi)
__device__ __forceinline__ void split_st(float f, __nv_bfloat16* ph, __nv_bfloat16* pl) {
    unsigned u = __float_as_uint(f);
    unsigned short hb = (unsigned short)(u >> 16);
    float hf = __uint_as_float(u & 0xFFFF0000u);
    __nv_bfloat16 h; memcpy(&h, &hb, 2);
    *ph = h;
    *pl = __float2bfloat16(f - hf);
}

// ==================== main solve kernel =====================================
// 1 warp = 32 problems. GEMM1: Y(64x8/tile) = G(64x32)@B ; tanh ; GEMM2:
// B'(32x8) = C^T(32x64)@F. G/C fragments in registers; B/F staged in smem.
__global__ void __launch_bounds__(128, 2) solve_kernel(
    const float* __restrict__ y_init, const float* __restrict__ Bin,
    const float* __restrict__ a, float* __restrict__ out)
{
    __shared__ alignas(16) __nv_bfloat16 sB[4][2][32*BSS];
    __shared__ alignas(16) __nv_bfloat16 sF[4][2][8*FSS];

    int tid  = threadIdx.x;
    int wid  = tid >> 5;
    int lane = tid & 31;
    int g = lane >> 2, t = lane & 3;

    // ---- A fragments (constant): G (2 kt x 4 mt), C^T (4 kt x 2 mt) ----
    unsigned Gh[2][4][4], Gl[2][4][4];
    #pragma unroll
    for (int kt = 0; kt < 2; kt++)
        #pragma unroll
        for (int mt = 0; mt < 4; mt++) {
            int r0 = (mt*16 + g)*GS + kt*8 + t;
            Gh[kt][mt][0] = __ldg(&g_Ghi[r0]);
            Gh[kt][mt][1] = __ldg(&g_Ghi[r0 + 8*GS]);
            Gh[kt][mt][2] = __ldg(&g_Ghi[r0 + 4]);
            Gh[kt][mt][3] = __ldg(&g_Ghi[r0 + 8*GS + 4]);
            Gl[kt][mt][0] = __ldg(&g_Glo[r0]);
            Gl[kt][mt][1] = __ldg(&g_Glo[r0 + 8*GS]);
            Gl[kt][mt][2] = __ldg(&g_Glo[r0 + 4]);
            Gl[kt][mt][3] = __ldg(&g_Glo[r0 + 8*GS + 4]);
        }
    unsigned Ch[4][2][4], Cl[4][2][4];
    #pragma unroll
    for (int kt = 0; kt < 4; kt++)
        #pragma unroll
        for (int mt = 0; mt < 2; mt++) {
            int r0 = (mt*16 + g)*CS + kt*8 + t;
            Ch[kt][mt][0] = __ldg(&g_Chi[r0]);
            Ch[kt][mt][1] = __ldg(&g_Chi[r0 + 8*CS]);
            Ch[kt][mt][2] = __ldg(&g_Chi[r0 + 4]);
            Ch[kt][mt][3] = __ldg(&g_Chi[r0 + 8*CS + 4]);
            Cl[kt][mt][0] = __ldg(&g_Clo[r0]);
            Cl[kt][mt][1] = __ldg(&g_Clo[r0 + 8*CS]);
            Cl[kt][mt][2] = __ldg(&g_Clo[r0 + 4]);
            Cl[kt][mt][3] = __ldg(&g_Clo[r0 + 8*CS + 4]);
        }

    // ---- per-thread row constants (rows g + 8j) ----
    float sin_r[8], tc1_r[8];
    #pragma unroll
    for (int j = 0; j < 8; j++) {
        sin_r[j] = __ldg(&c_sin[g + 8*j]);
        tc1_r[j] = __ldg(&c_tc1[g + 8*j]);
    }
    float V_r[4];
    #pragma unroll
    for (int j = 0; j < 4; j++) V_r[j] = __ldg(&c_V[g + 8*j]);
    float invs = __ldg(&c_scal[0]);
    float sin0 = __ldg(&c_scal[1]);

    // ---- own problem (column = lane) ----
    int pbase = blockIdx.x * 128 + wid * 32;
    int pcol  = pbase + lane;
    float y0  = y_init[pcol];
    float aj0 = __ldg(&a[pcol & 511]);
    float w0  = (sin0 - fast_tanh(y0 * aj0)) * invs;

    // ---- initial B staging (lane writes its own column, split hi/lo) ----
    {
        const float* bp = Bin + (long)pcol * NB;
        __nv_bfloat16* bh = &sB[wid][0][lane*BSS];
        __nv_bfloat16* bl = &sB[wid][1][lane*BSS];
        #pragma unroll 1
        for (int m = 0; m < NB; m++) split_st(bp[m], &bh[m], &bl[m]);
        __nv_bfloat16 z = __float2bfloat16(0.f);
        bh[30] = z; bh[31] = z; bl[30] = z; bl[31] = z;
    }
    __syncwarp();

    #pragma unroll 1
    for (int it = 0; it < NITER; it++) {
        #pragma unroll 1
        for (int nt = 0; nt < 4; nt++) {
            // column data for this thread's two fragment columns
            int c0l = nt*8 + 2*t;
            float yn0 = __shfl_sync(0xffffffffu, y0,  c0l);
            float yn1 = __shfl_sync(0xffffffffu, y0,  c0l + 1);
            float wn0 = __shfl_sync(0xffffffffu, w0,  c0l);
            float wn1 = __shfl_sync(0xffffffffu, w0,  c0l + 1);
            float an0 = __shfl_sync(0xffffffffu, aj0, c0l);
            float an1 = __shfl_sync(0xffffffffu, aj0, c0l + 1);

            // ---- GEMM1: Y = G @ B(:, tile nt) ----
            float acc[4][4];
            #pragma unroll
            for (int mt = 0; mt < 4; mt++)
                #pragma unroll
                for (int r = 0; r < 4; r++) acc[mt][r] = 0.f;

            #pragma unroll
            for (int kt = 0; kt < 2; kt++) {
                int boff = (nt*8 + g)*BSS + kt*16 + 2*t;
                unsigned bh0 = *(const unsigned*)&sB[wid][0][boff];
                unsigned bh1 = *(const unsigned*)&sB[wid][0][boff + 8];
                unsigned bl0 = *(const unsigned*)&sB[wid][1][boff];
                unsigned bl1 = *(const unsigned*)&sB[wid][1][boff + 8];
                #pragma unroll
                for (int mt = 0; mt < 4; mt++) {
                    mma_bf16(acc[mt], Gh[kt][mt][0], Gh[kt][mt][1], Gh[kt][mt][2], Gh[kt][mt][3], bh0, bh1);
                    mma_bf16(acc[mt], Gh[kt][mt][0], Gh[kt][mt][1], Gh[kt][mt][2], Gh[kt][mt][3], bl0, bl1);
                    mma_bf16(acc[mt], Gl[kt][mt][0], Gl[kt][mt][1], Gl[kt][mt][2], Gl[kt][mt][3], bh0, bh1);
                }
            }

            // ---- elementwise: ya -> f -> split -> F staging ----
            #pragma unroll
            for (int mt = 0; mt < 4; mt++) {
                #pragma unroll
                for (int r = 0; r < 4; r++) {
                    int s = r >> 1, colsel = r & 1;
                    int j = 2*mt + s;                  // point row = g + 8j
                    float yv = colsel ? yn1 : yn0;
                    float wv = colsel ? wn1 : wn0;
                    float av = colsel ? an1 : an0;
                    float ya = acc[mt][r] + fmaf(wv, tc1_r[j], yv);
                    float f  = sin_r[j] - fast_tanh(ya * av);
                    int cl = 2*t + colsel;
                    int krow = g + 8*j;
                    split_st(f, &sF[wid][0][cl*FSS + krow], &sF[wid][1][cl*FSS + krow]);
                }
            }
            __syncwarp();

            // ---- GEMM2: Bnew = C^T @ F ----
            float acc2[2][4];
            #pragma unroll
            for (int mt = 0; mt < 2; mt++)
                #pragma unroll
                for (int r = 0; r < 4; r++) acc2[mt][r] = 0.f;

            #pragma unroll
            for (int kt = 0; kt < 4; kt++) {
                int foff = g*FSS + kt*16 + 2*t;
                unsigned fh0 = *(const unsigned*)&sF[wid][0][foff];
                unsigned fh1 = *(const unsigned*)&sF[wid][0][foff + 8];
                unsigned fl0 = *(const unsigned*)&sF[wid][1][foff];
                unsigned fl1 = *(const unsigned*)&sF[wid][1][foff + 8];
                #pragma unroll
                for (int mt = 0; mt < 2; mt++) {
                    mma_bf16(acc2[mt], Ch[kt][mt][0], Ch[kt][mt][1], Ch[kt][mt][2], Ch[kt][mt][3], fh0, fh1);
                    mma_bf16(acc2[mt], Ch[kt][mt][0], Ch[kt][mt][1], Ch[kt][mt][2], Ch[kt][mt][3], fl0, fl1);
                    mma_bf16(acc2[mt], Cl[kt][mt][0], Cl[kt][mt][1], Cl[kt][mt][2], Cl[kt][mt][3], fh0, fh1);
                }
            }
            __syncwarp();   // F reads done before next nt overwrites; B reads done before writes below

            // ---- B update + staging write ----
            #pragma unroll
            for (int mt = 0; mt < 2; mt++) {
                #pragma unroll
                for (int r = 0; r < 4; r++) {
                    int s = r >> 1, colsel = r & 1;
                    int j2 = 2*mt + s;                 // coef m = g + 8*j2
                    int m  = g + 8*j2;
                    float wv = colsel ? wn1 : wn0;
                    float Bv = fmaf(invs, acc2[mt][r], -(wv * V_r[j2]));
                    int nabs = nt*8 + 2*t + colsel;
                    split_st(Bv, &sB[wid][0][nabs*BSS + m], &sB[wid][1][nabs*BSS + m]);
                }
            }
            __syncwarp();
        } // nt
    } // it

    // ==================== epilogue (lane = its own column) ==================
    float Bf[NB];
    {
        const __nv_bfloat16* bh = &sB[wid][0][lane*BSS];
        const __nv_bfloat16* bl = &sB[wid][1][lane*BSS];
        #pragma unroll
        for (int m = 0; m < NB; m++)
            Bf[m] = __bfloat162float(bh[m]) + __bfloat162float(bl[m]);
    }

    float h0 = y0 + w0, h1 = w0;
    #pragma unroll
    for (int m = 0; m < NB; m++) {
        h0 = fmaf(-Bf[m], __ldg(&c_P0[m]), h0);
        h1 = fmaf(-Bf[m], __ldg(&c_P1[m]), h1);
    }

    float* outB = out + 16L*NPROB;
    {
        float* dst = outB + (long)pcol * NCF;
        dst[0] = h0; dst[1] = h1;
        #pragma unroll
        for (int m = 0; m < NB; m++) dst[2+m] = Bf[m];
    }

    #pragma unroll 1
    for (int tt = 0; tt < 16; tt++) {
        float val = fmaf(h0, __ldg(&c_PO[0][tt]), h1 * __ldg(&c_PO[1][tt]));
        #pragma unroll
        for (int m = 0; m < NB; m++)
            val = fmaf(Bf[m], __ldg(&c_PO[m+2][tt]), val);
        out[(long)tt*NPROB + pcol] = val;
    }
}

// ==================== launch ================================================
extern "C" void kernel_launch(void* const* d_in, const int* in_sizes, int n_in,
                              void* d_out, int out_size) {
    const float* y_init = (const float*)d_in[0];
    const float* B_init = (const float*)d_in[1];
    const float* t_span = (const float*)d_in[2];
    const float* a      = (const float*)d_in[3];
    float* out = (float*)d_out;
    setup_kernel<<<1, 256>>>(t_span);
    solve_kernel<<<NPROB/128, 128>>>(y_init, B_init, a, out);
}

// round 9
// speedup vs baseline: 2.3099x; 1.1203x over previous
#include <cuda_runtime.h>
#include <cuda_bf16.h>
#include <math.h>

#define NPTS 64
#define NCF  32
#define NB   30
#define NITER 20
#define NPROB (256*512)
#define PI_D 3.14159265358979323846

#define BSS 40   // bf16 per column of B staging (32 + 8 pad)
#define FSS 72   // bf16 per column of F staging (64 + 8 pad)

// ------------------------ device scratch (double, setup only) ---------------
__device__ double scr_T[NCF][NPTS];
__device__ double scr_DT[NCF][NPTS];
__device__ double scr_Gb[NB][NPTS];
__device__ double scr_M[NB][2*NB];
__device__ double scr_Cd[NPTS][NB];
__device__ double scr_tch[NPTS];
__device__ double scr_Dt[NPTS];
__device__ double scr_P0[NB], scr_P1[NB];

// ------------------------ constants for solve kernel ------------------------
// Fragment-order packed A matrices (thread-major: one uint4 per lane per (kt,mt))
// G frags: [hi/lo][kt(2)][mt(4)][lane(32)*4+w] ; C frags: [hi/lo][kt(4)][mt(2)][...]
__device__ unsigned g_Gfrag[2*2*4*32*4];   // 2048 words
__device__ unsigned g_Cfrag[2*4*2*32*4];   // 2048 words
__device__ float c_sin[NPTS], c_tc1[NPTS];
__device__ float c_V[NCF], c_P0[NCF], c_P1[NCF];
__device__ float c_PO[NCF][16];
__device__ float c_scal[2];          // inv_s, sin(t0)

// ==================== setup kernel: 1 block, 256 threads, fp64 ==============
__global__ void setup_kernel(const float* __restrict__ tspan) {
    int tid = threadIdx.x;
    double t0 = (double)tspan[0];
    double t1 = (double)tspan[15];
    double inv_s = 0.5 * (t1 - t0);
    __shared__ int s_piv;
    __shared__ double s_fac[NB];

    if (tid < NPTS) scr_tch[tid] = -cos(PI_D * (double)tid / (double)NPTS);
    __syncthreads();
    if (tid < NPTS) {
        double tnext = (tid == NPTS-1) ? 1.0 : scr_tch[tid+1];
        scr_Dt[tid]  = tnext - scr_tch[tid];
        double t = scr_tch[tid];
        double Tm2 = 1.0, Tm1 = t;
        scr_T[0][tid] = 1.0; scr_T[1][tid] = t;
        #pragma unroll 1
        for (int n = 2; n < NCF; n++) {
            double Tn = 2.0*t*Tm1 - Tm2; scr_T[n][tid] = Tn; Tm2 = Tm1; Tm1 = Tn;
        }
        double Ua = 1.0, Ub = 2.0*t;
        scr_DT[0][tid] = 0.0;
        scr_DT[1][tid] = 1.0;
        scr_DT[2][tid] = 2.0*Ub;
        #pragma unroll 1
        for (int n = 3; n < NCF; n++) {
            double Uc = 2.0*t*Ub - Ua;
            scr_DT[n][tid] = (double)n * Uc;
            Ua = Ub; Ub = Uc;
        }
    }
    __syncthreads();

    if (tid < NB) {
        double d0 = scr_DT[tid+2][0];
        scr_P1[tid] = d0;
        scr_P0[tid] = scr_T[tid+2][0] + d0;
    }
    __syncthreads();

    for (int e = tid; e < NB*NPTS; e += blockDim.x) {
        int m = e / NPTS, k = e % NPTS;
        scr_Gb[m][k] = scr_DT[m+2][k] - scr_P1[m];
    }
    __syncthreads();

    for (int e = tid; e < NB*NB; e += blockDim.x) {
        int i = e / NB, j = e % NB;
        double s = 0.0;
        for (int k = 0; k < NPTS; k++) s += scr_Gb[i][k]*scr_Dt[k]*scr_Gb[j][k];
        scr_M[i][j] = s;
        scr_M[i][NB+j] = (i == j) ? 1.0 : 0.0;
    }
    __syncthreads();

    for (int col = 0; col < NB; col++) {
        if (tid == 0) {
            int p = col; double best = fabs(scr_M[col][col]);
            for (int r = col+1; r < NB; r++) {
                double v = fabs(scr_M[r][col]);
                if (v > best) { best = v; p = r; }
            }
            s_piv = p;
        }
        __syncthreads();
        int p = s_piv;
        if (p != col && tid < 2*NB) {
            double tmp = scr_M[col][tid]; scr_M[col][tid] = scr_M[p][tid]; scr_M[p][tid] = tmp;
        }
        __syncthreads();
        double piv = scr_M[col][col];
        __syncthreads();
        if (tid < 2*NB) scr_M[col][tid] = scr_M[col][tid] / piv;
        if (tid < NB)   s_fac[tid] = scr_M[tid][col];
        __syncthreads();
        for (int e = tid; e < NB*2*NB; e += blockDim.x) {
            int r = e / (2*NB), c = e % (2*NB);
            if (r != col) scr_M[r][c] -= s_fac[r] * scr_M[col][c];
        }
        __syncthreads();
    }

    for (int e = tid; e < NPTS*NB; e += blockDim.x) {
        int k = e / NB, m = e % NB;
        double s = 0.0;
        for (int j = 0; j < NB; j++) s += scr_Gb[j][k] * scr_M[j][NB+m];
        scr_Cd[k][m] = scr_Dt[k] * s;
    }
    __syncthreads();

    // ---- G fragments (thread-major): e -> (kt, mt, lane, w) ----
    for (int e = tid; e < 1024; e += blockDim.x) {
        int kt = e >> 9, rem = e & 511;
        int mt = rem >> 7, rem2 = rem & 127;
        int lane = rem2 >> 2, w = rem2 & 3;
        int g = lane >> 2, t = lane & 3;
        int row = mt*16 + ((w & 1) ? 8 : 0) + g;              // point
        int cp  = kt*8 + ((w & 2) ? 4 : 0) + t;               // coef pair
        int m0 = 2*cp, m1 = 2*cp + 1;
        float f0 = 0.f, f1 = 0.f;
        if (m0 < NB) f0 = (float)(scr_T[m0+2][row] - scr_P0[m0] - scr_P1[m0]*scr_tch[row]);
        if (m1 < NB) f1 = (float)(scr_T[m1+2][row] - scr_P0[m1] - scr_P1[m1]*scr_tch[row]);
        __nv_bfloat16 h0 = __float2bfloat16(f0), h1 = __float2bfloat16(f1);
        __nv_bfloat16 l0 = __float2bfloat16(f0 - __bfloat162float(h0));
        __nv_bfloat16 l1 = __float2bfloat16(f1 - __bfloat162float(h1));
        unsigned short b; unsigned wh, wl;
        memcpy(&b, &h0, 2); wh = b;
        memcpy(&b, &h1, 2); wh |= (unsigned)b << 16;
        memcpy(&b, &l0, 2); wl = b;
        memcpy(&b, &l1, 2); wl |= (unsigned)b << 16;
        g_Gfrag[e]        = wh;
        g_Gfrag[1024 + e] = wl;
    }
    // ---- C^T fragments: e -> (kt, mt, lane, w) ----
    for (int e = tid; e < 1024; e += blockDim.x) {
        int kt = e >> 8;
        int mt = (e >> 7) & 1;
        int lane = (e >> 2) & 31, w = e & 3;
        int g = lane >> 2, t = lane & 3;
        int row = mt*16 + ((w & 1) ? 8 : 0) + g;              // coef m
        int cp  = kt*8 + ((w & 2) ? 4 : 0) + t;               // point pair
        float f0 = 0.f, f1 = 0.f;
        if (row < NB) { f0 = (float)scr_Cd[2*cp][row]; f1 = (float)scr_Cd[2*cp+1][row]; }
        __nv_bfloat16 h0 = __float2bfloat16(f0), h1 = __float2bfloat16(f1);
        __nv_bfloat16 l0 = __float2bfloat16(f0 - __bfloat162float(h0));
        __nv_bfloat16 l1 = __float2bfloat16(f1 - __bfloat162float(h1));
        unsigned short b; unsigned wh, wl;
        memcpy(&b, &h0, 2); wh = b;
        memcpy(&b, &h1, 2); wh |= (unsigned)b << 16;
        memcpy(&b, &l0, 2); wl = b;
        memcpy(&b, &l1, 2); wl |= (unsigned)b << 16;
        g_Cfrag[e]        = wh;
        g_Cfrag[1024 + e] = wl;
    }

    if (tid < NCF) {
        double v = 0.0, p0 = 0.0, p1 = 0.0;
        if (tid < NB) {
            for (int k = 0; k < NPTS; k++) v += scr_Cd[k][tid];
            p0 = scr_P0[tid]; p1 = scr_P1[tid];
        }
        c_V[tid] = (float)v; c_P0[tid] = (float)p0; c_P1[tid] = (float)p1;
    }
    if (tid < NPTS) {
        c_tc1[tid] = (float)(1.0 + scr_tch[tid]);
        c_sin[tid] = (float)sin(t0 + inv_s * (scr_tch[tid] + 1.0));
    }
    if (tid == 0) { c_scal[0] = (float)inv_s; c_scal[1] = (float)sin(t0); }
    if (tid < 16) {
        double tq = -1.0 + 2.0*((double)tspan[tid] - t0)/(t1 - t0);
        double Tm2 = 1.0, Tm1 = tq;
        c_PO[0][tid] = 1.0f; c_PO[1][tid] = (float)tq;
        #pragma unroll 1
        for (int n = 2; n < NCF; n++) {
            double Tn = 2.0*tq*Tm1 - Tm2; c_PO[n][tid] = (float)Tn; Tm2 = Tm1; Tm1 = Tn;
        }
    }
}

// ==================== solve kernel helpers ==================================
__device__ __forceinline__ float fast_tanh(float x) {
    float ax = fabsf(x);
    float e  = __expf(-2.0f * ax);
    float t  = __fdividef(1.0f - e, 1.0f + e);
    return copysignf(t, x);
}

__device__ __forceinline__ void mma_bf16(float* d,
    unsigned a0, unsigned a1, unsigned a2, unsigned a3,
    unsigned b0, unsigned b1)
{
    asm("mma.sync.aligned.m16n8k16.row.col.f32.bf16.bf16.f32 "
        "{%0,%1,%2,%3}, {%4,%5,%6,%7}, {%8,%9}, {%0,%1,%2,%3};"
        : "+f"(d[0]), "+f"(d[1]), "+f"(d[2]), "+f"(d[3])
        : "r"(a0), "r"(a1), "r"(a2), "r"(a3), "r"(b0), "r"(b1));
}

// truncation split: hi = f with low 16 bits zeroed, lo = rn(f - hi)
__device__ __forceinline__ void split_st(float f, __nv_bfloat16* ph, __nv_bfloat16* pl) {
    unsigned u = __float_as_uint(f);
    unsigned short hb = (unsigned short)(u >> 16);
    float hf = __uint_as_float(u & 0xFFFF0000u);
    __nv_bfloat16 h; memcpy(&h, &hb, 2);
    *ph = h;
    *pl = __float2bfloat16(f - hf);
}

// ==================== main solve kernel =====================================
// 1 warp = 32 problems. A fragments live in block-shared smem (thread-major,
// one LDS.128 per (kt,mt) per hi/lo). B/F staged per-warp in smem.
__global__ void __launch_bounds__(128, 4) solve_kernel(
    const float* __restrict__ y_init, const float* __restrict__ Bin,
    const float* __restrict__ a, float* __restrict__ out)
{
    __shared__ alignas(16) __nv_bfloat16 sB[4][2][32*BSS];
    __shared__ alignas(16) __nv_bfloat16 sF[4][2][8*FSS];
    __shared__ alignas(16) unsigned sGf[2048];   // [hi/lo][kt][mt][lane*4+w]
    __shared__ alignas(16) unsigned sCf[2048];

    int tid  = threadIdx.x;
    int wid  = tid >> 5;
    int lane = tid & 31;
    int g = lane >> 2, t = lane & 3;

    // copy fragment tables (block-shared, read-only)
    {
        const uint4* gsrc = (const uint4*)g_Gfrag;
        const uint4* csrc = (const uint4*)g_Cfrag;
        uint4* gdst = (uint4*)sGf;
        uint4* cdst = (uint4*)sCf;
        for (int e = tid; e < 512; e += 128) { gdst[e] = gsrc[e]; cdst[e] = csrc[e]; }
    }

    // ---- per-thread row constants (rows g + 8j) ----
    float sin_r[8], tc1_r[8];
    #pragma unroll
    for (int j = 0; j < 8; j++) {
        sin_r[j] = __ldg(&c_sin[g + 8*j]);
        tc1_r[j] = __ldg(&c_tc1[g + 8*j]);
    }
    float V_r[4];
    #pragma unroll
    for (int j = 0; j < 4; j++) V_r[j] = __ldg(&c_V[g + 8*j]);
    float invs = __ldg(&c_scal[0]);
    float sin0 = __ldg(&c_scal[1]);

    // ---- own problem (column = lane) ----
    int pbase = blockIdx.x * 128 + wid * 32;
    int pcol  = pbase + lane;
    float y0  = y_init[pcol];
    float aj0 = __ldg(&a[pcol & 511]);
    float w0  = (sin0 - fast_tanh(y0 * aj0)) * invs;

    // ---- initial B staging ----
    {
        const float* bp = Bin + (long)pcol * NB;
        __nv_bfloat16* bh = &sB[wid][0][lane*BSS];
        __nv_bfloat16* bl = &sB[wid][1][lane*BSS];
        #pragma unroll 1
        for (int m = 0; m < NB; m++) split_st(bp[m], &bh[m], &bl[m]);
        __nv_bfloat16 z = __float2bfloat16(0.f);
        bh[30] = z; bh[31] = z; bl[30] = z; bl[31] = z;
    }
    __syncthreads();   // also covers fragment-table copy

    #pragma unroll 1
    for (int it = 0; it < NITER; it++) {
        #pragma unroll 1
        for (int nt = 0; nt < 4; nt++) {
            int c0l = nt*8 + 2*t;
            float yn0 = __shfl_sync(0xffffffffu, y0,  c0l);
            float yn1 = __shfl_sync(0xffffffffu, y0,  c0l + 1);
            float wn0 = __shfl_sync(0xffffffffu, w0,  c0l);
            float wn1 = __shfl_sync(0xffffffffu, w0,  c0l + 1);
            float an0 = __shfl_sync(0xffffffffu, aj0, c0l);
            float an1 = __shfl_sync(0xffffffffu, aj0, c0l + 1);

            // ---- GEMM1: Y = G @ B(:, tile nt) ----
            float acc[4][4];
            #pragma unroll
            for (int mt = 0; mt < 4; mt++)
                #pragma unroll
                for (int r = 0; r < 4; r++) acc[mt][r] = 0.f;

            #pragma unroll
            for (int kt = 0; kt < 2; kt++) {
                int boff = (nt*8 + g)*BSS + kt*16 + 2*t;
                unsigned bh0 = *(const unsigned*)&sB[wid][0][boff];
                unsigned bh1 = *(const unsigned*)&sB[wid][0][boff + 8];
                unsigned bl0 = *(const unsigned*)&sB[wid][1][boff];
                unsigned bl1 = *(const unsigned*)&sB[wid][1][boff + 8];
                #pragma unroll
                for (int mt = 0; mt < 4; mt++) {
                    int fi = ((kt*4 + mt)*32 + lane)*4;
                    uint4 ah = *(const uint4*)&sGf[fi];
                    uint4 al = *(const uint4*)&sGf[1024 + fi];
                    mma_bf16(acc[mt], ah.x, ah.y, ah.z, ah.w, bh0, bh1);
                    mma_bf16(acc[mt], ah.x, ah.y, ah.z, ah.w, bl0, bl1);
                    mma_bf16(acc[mt], al.x, al.y, al.z, al.w, bh0, bh1);
                }
            }

            // ---- elementwise: ya -> f -> split -> F staging ----
            #pragma unroll
            for (int mt = 0; mt < 4; mt++) {
                #pragma unroll
                for (int r = 0; r < 4; r++) {
                    int s = r >> 1, colsel = r & 1;
                    int j = 2*mt + s;
                    float yv = colsel ? yn1 : yn0;
                    float wv = colsel ? wn1 : wn0;
                    float av = colsel ? an1 : an0;
                    float ya = acc[mt][r] + fmaf(wv, tc1_r[j], yv);
                    float f  = sin_r[j] - fast_tanh(ya * av);
                    int cl = 2*t + colsel;
                    int krow = g + 8*j;
                    split_st(f, &sF[wid][0][cl*FSS + krow], &sF[wid][1][cl*FSS + krow]);
                }
            }
            __syncwarp();

            // ---- GEMM2: Bnew = C^T @ F ----
            float acc2[2][4];
            #pragma unroll
            for (int mt = 0; mt < 2; mt++)
                #pragma unroll
                for (int r = 0; r < 4; r++) acc2[mt][r] = 0.f;

            #pragma unroll
            for (int kt = 0; kt < 4; kt++) {
                int foff = g*FSS + kt*16 + 2*t;
                unsigned fh0 = *(const unsigned*)&sF[wid][0][foff];
                unsigned fh1 = *(const unsigned*)&sF[wid][0][foff + 8];
                unsigned fl0 = *(const unsigned*)&sF[wid][1][foff];
                unsigned fl1 = *(const unsigned*)&sF[wid][1][foff + 8];
                #pragma unroll
                for (int mt = 0; mt < 2; mt++) {
                    int fi = ((kt*2 + mt)*32 + lane)*4;
                    uint4 ah = *(const uint4*)&sCf[fi];
                    uint4 al = *(const uint4*)&sCf[1024 + fi];
                    mma_bf16(acc2[mt], ah.x, ah.y, ah.z, ah.w, fh0, fh1);
                    mma_bf16(acc2[mt], ah.x, ah.y, ah.z, ah.w, fl0, fl1);
                    mma_bf16(acc2[mt], al.x, al.y, al.z, al.w, fh0, fh1);
                }
            }
            __syncwarp();

            // ---- B update + staging write ----
            #pragma unroll
            for (int mt = 0; mt < 2; mt++) {
                #pragma unroll
                for (int r = 0; r < 4; r++) {
                    int s = r >> 1, colsel = r & 1;
                    int j2 = 2*mt + s;
                    int m  = g + 8*j2;
                    float wv = colsel ? wn1 : wn0;
                    float Bv = fmaf(invs, acc2[mt][r], -(wv * V_r[j2]));
                    int nabs = nt*8 + 2*t + colsel;
                    split_st(Bv, &sB[wid][0][nabs*BSS + m], &sB[wid][1][nabs*BSS + m]);
                }
            }
            __syncwarp();
        } // nt
    } // it

    // ==================== epilogue (lane = its own column) ==================
    float Bf[NB];
    {
        const __nv_bfloat16* bh = &sB[wid][0][lane*BSS];
        const __nv_bfloat16* bl = &sB[wid][1][lane*BSS];
        #pragma unroll
        for (int m = 0; m < NB; m++)
            Bf[m] = __bfloat162float(bh[m]) + __bfloat162float(bl[m]);
    }

    float h0 = y0 + w0, h1 = w0;
    #pragma unroll
    for (int m = 0; m < NB; m++) {
        h0 = fmaf(-Bf[m], __ldg(&c_P0[m]), h0);
        h1 = fmaf(-Bf[m], __ldg(&c_P1[m]), h1);
    }

    float* outB = out + 16L*NPROB;
    {
        float* dst = outB + (long)pcol * NCF;
        dst[0] = h0; dst[1] = h1;
        #pragma unroll
        for (int m = 0; m < NB; m++) dst[2+m] = Bf[m];
    }

    #pragma unroll 1
    for (int tt = 0; tt < 16; tt++) {
        float val = fmaf(h0, __ldg(&c_PO[0][tt]), h1 * __ldg(&c_PO[1][tt]));
        #pragma unroll
        for (int m = 0; m < NB; m++)
            val = fmaf(Bf[m], __ldg(&c_PO[m+2][tt]), val);
        out[(long)tt*NPROB + pcol] = val;
    }
}

// ==================== launch ================================================
extern "C" void kernel_launch(void* const* d_in, const int* in_sizes, int n_in,
                              void* d_out, int out_size) {
    const float* y_init = (const float*)d_in[0];
    const float* B_init = (const float*)d_in[1];
    const float* t_span = (const float*)d_in[2];
    const float* a      = (const float*)d_in[3];
    float* out = (float*)d_out;
    setup_kernel<<<1, 256>>>(t_span);
    solve_kernel<<<NPROB/128, 128>>>(y_init, B_init, a, out);
}

// round 10
// speedup vs baseline: 3.0672x; 1.3278x over previous
#include <cuda_runtime.h>
#include <cuda_bf16.h>
#include <math.h>

#define NPTS 64
#define NCF  32
#define NB   30
#define NITER 20
#define NPROB (256*512)
#define PI_D 3.14159265358979323846

#define BSS 40   // bf16 per column of B staging (32 + 8 pad)
#define FSS 72   // bf16 per column of F staging (64 + 8 pad)

// ===================== compile-time constant tables (R4-proven) =============
struct Tbl {
    float G[NPTS][NB];   // G[k][m] = T[m+2](tch_k) - P0[m] - P1[m]*tch_k
    float C[NPTS][NB];   // Phi_c^T
    float V[NB];
    float P0[NB], P1[NB];
    float TC1[NPTS];     // 1 + tch[k]
};

constexpr double ccos(double x) {
    double x2 = x * x, term = 1.0, s = 1.0;
    for (int n = 1; n <= 25; n++) { term *= -x2 / ((2.0*n - 1.0) * (2.0*n)); s += term; }
    return s;
}

constexpr Tbl make_tbl() {
    Tbl R{};
    double tch[NPTS] = {}, Dt[NPTS] = {};
    for (int k = 0; k < NPTS; k++) tch[k] = -ccos(PI_D * (double)k / (double)NPTS);
    for (int k = 0; k < NPTS; k++) {
        double tn = (k == NPTS-1) ? 1.0 : tch[k+1];
        Dt[k] = tn - tch[k];
    }
    double T[NCF][NPTS] = {}, DT[NCF][NPTS] = {};
    for (int k = 0; k < NPTS; k++) {
        double t = tch[k];
        T[0][k] = 1.0; T[1][k] = t;
        for (int n = 2; n < NCF; n++) T[n][k] = 2.0*t*T[n-1][k] - T[n-2][k];
        double Ua = 1.0, Ub = 2.0*t;
        DT[0][k] = 0.0; DT[1][k] = 1.0; DT[2][k] = 2.0*Ub;
        for (int n = 3; n < NCF; n++) {
            double Uc = 2.0*t*Ub - Ua;
            DT[n][k] = (double)n * Uc;
            Ua = Ub; Ub = Uc;
        }
    }
    double P0[NB] = {}, P1[NB] = {};
    for (int m = 0; m < NB; m++) { double d0 = DT[m+2][0]; P1[m] = d0; P0[m] = T[m+2][0] + d0; }
    double Gb[NB][NPTS] = {};
    for (int m = 0; m < NB; m++)
        for (int k = 0; k < NPTS; k++) Gb[m][k] = DT[m+2][k] - P1[m];
    double M[NB][2*NB] = {};
    for (int i = 0; i < NB; i++)
        for (int j = 0; j < NB; j++) {
            double s = 0.0;
            for (int k = 0; k < NPTS; k++) s += Gb[i][k]*Dt[k]*Gb[j][k];
            M[i][j] = s;
            M[i][NB+j] = (i == j) ? 1.0 : 0.0;
        }
    for (int col = 0; col < NB; col++) {
        int p = col; double best = M[col][col] < 0 ? -M[col][col] : M[col][col];
        for (int r = col+1; r < NB; r++) {
            double v = M[r][col] < 0 ? -M[r][col] : M[r][col];
            if (v > best) { best = v; p = r; }
        }
        if (p != col)
            for (int c = 0; c < 2*NB; c++) { double tmp = M[col][c]; M[col][c] = M[p][c]; M[p][c] = tmp; }
        double piv = M[col][col];
        for (int c = 0; c < 2*NB; c++) M[col][c] /= piv;
        for (int r = 0; r < NB; r++) if (r != col) {
            double f = M[r][col];
            for (int c = 0; c < 2*NB; c++) M[r][c] -= f * M[col][c];
        }
    }
    double Cd[NPTS][NB] = {};
    for (int k = 0; k < NPTS; k++)
        for (int m = 0; m < NB; m++) {
            double s = 0.0;
            for (int j = 0; j < NB; j++) s += Gb[j][k] * M[j][NB+m];
            Cd[k][m] = Dt[k] * s;
        }
    for (int k = 0; k < NPTS; k++)
        for (int m = 0; m < NB; m++) {
            R.G[k][m] = (float)(T[m+2][k] - P0[m] - P1[m]*tch[k]);
            R.C[k][m] = (float)Cd[k][m];
        }
    for (int m = 0; m < NB; m++) {
        double v = 0.0;
        for (int k = 0; k < NPTS; k++) v += Cd[k][m];
        R.V[m] = (float)v; R.P0[m] = (float)P0[m]; R.P1[m] = (float)P1[m];
    }
    for (int k = 0; k < NPTS; k++) R.TC1[k] = (float)(1.0 + tch[k]);
    return R;
}

__device__ constexpr Tbl d_TB = make_tbl();

// ------------------------ runtime-filled constants --------------------------
// Fragment-order packed A matrices (thread-major: one uint4 per lane per (kt,mt))
__device__ unsigned g_Gfrag[2048];   // [hi(0)/lo(1024)][kt(2)][mt(4)][lane*4+w]
__device__ unsigned g_Cfrag[2048];   // [hi/lo][kt(4)][mt(2)][lane*4+w]
__device__ float c_sin[NPTS];
__device__ float c_V[NCF];           // zero-padded V
__device__ float c_PO[NCF][16];
__device__ float c_scal[2];          // inv_s, sin(t0)

// ==================== setup kernel: tiny (runtime-only parts) ===============
__global__ void setup_kernel(const float* __restrict__ tspan) {
    int tid = threadIdx.x;
    double t0 = (double)tspan[0];
    double t1 = (double)tspan[15];
    double inv_s = 0.5 * (t1 - t0);

    // ---- G fragments (thread-major): e -> (kt, mt, lane, w) ----
    for (int e = tid; e < 1024; e += blockDim.x) {
        int kt = e >> 9, rem = e & 511;
        int mt = rem >> 7, rem2 = rem & 127;
        int lane = rem2 >> 2, w = rem2 & 3;
        int g = lane >> 2, t = lane & 3;
        int row = mt*16 + ((w & 1) ? 8 : 0) + g;
        int cp  = kt*8 + ((w & 2) ? 4 : 0) + t;
        int m0 = 2*cp, m1 = 2*cp + 1;
        float f0 = (m0 < NB) ? d_TB.G[row][m0] : 0.f;
        float f1 = (m1 < NB) ? d_TB.G[row][m1] : 0.f;
        __nv_bfloat16 h0 = __float2bfloat16(f0), h1 = __float2bfloat16(f1);
        __nv_bfloat16 l0 = __float2bfloat16(f0 - __bfloat162float(h0));
        __nv_bfloat16 l1 = __float2bfloat16(f1 - __bfloat162float(h1));
        unsigned short b; unsigned wh, wl;
        memcpy(&b, &h0, 2); wh = b;
        memcpy(&b, &h1, 2); wh |= (unsigned)b << 16;
        memcpy(&b, &l0, 2); wl = b;
        memcpy(&b, &l1, 2); wl |= (unsigned)b << 16;
        g_Gfrag[e]        = wh;
        g_Gfrag[1024 + e] = wl;
    }
    // ---- C^T fragments: e -> (kt, mt, lane, w) ----
    for (int e = tid; e < 1024; e += blockDim.x) {
        int kt = e >> 8;
        int mt = (e >> 7) & 1;
        int lane = (e >> 2) & 31, w = e & 3;
        int g = lane >> 2, t = lane & 3;
        int row = mt*16 + ((w & 1) ? 8 : 0) + g;     // coef m
        int cp  = kt*8 + ((w & 2) ? 4 : 0) + t;      // point pair
        float f0 = 0.f, f1 = 0.f;
        if (row < NB) { f0 = d_TB.C[2*cp][row]; f1 = d_TB.C[2*cp+1][row]; }
        __nv_bfloat16 h0 = __float2bfloat16(f0), h1 = __float2bfloat16(f1);
        __nv_bfloat16 l0 = __float2bfloat16(f0 - __bfloat162float(h0));
        __nv_bfloat16 l1 = __float2bfloat16(f1 - __bfloat162float(h1));
        unsigned short b; unsigned wh, wl;
        memcpy(&b, &h0, 2); wh = b;
        memcpy(&b, &h1, 2); wh |= (unsigned)b << 16;
        memcpy(&b, &l0, 2); wl = b;
        memcpy(&b, &l1, 2); wl |= (unsigned)b << 16;
        g_Cfrag[e]        = wh;
        g_Cfrag[1024 + e] = wl;
    }

    if (tid < NPTS) c_sin[tid] = (float)sin(t0 + inv_s * (double)d_TB.TC1[tid]);
    if (tid < NCF)  c_V[tid] = (tid < NB) ? d_TB.V[tid] : 0.f;
    if (tid == 0) { c_scal[0] = (float)inv_s; c_scal[1] = (float)sin(t0); }
    if (tid >= 64 && tid < 80) {
        int t = tid - 64;
        double tq = -1.0 + 2.0*((double)tspan[t] - t0)/(t1 - t0);
        double Tm2 = 1.0, Tm1 = tq;
        c_PO[0][t] = 1.0f; c_PO[1][t] = (float)tq;
        #pragma unroll 1
        for (int n = 2; n < NCF; n++) {
            double Tn = 2.0*tq*Tm1 - Tm2; c_PO[n][t] = (float)Tn; Tm2 = Tm1; Tm1 = Tn;
        }
    }
}

// ==================== solve kernel helpers ==================================
__device__ __forceinline__ float fast_tanh(float x) {
    float ax = fabsf(x);
    float e  = __expf(-2.0f * ax);
    float t  = __fdividef(1.0f - e, 1.0f + e);
    return copysignf(t, x);
}

__device__ __forceinline__ void mma_bf16(float* d,
    unsigned a0, unsigned a1, unsigned a2, unsigned a3,
    unsigned b0, unsigned b1)
{
    asm("mma.sync.aligned.m16n8k16.row.col.f32.bf16.bf16.f32 "
        "{%0,%1,%2,%3}, {%4,%5,%6,%7}, {%8,%9}, {%0,%1,%2,%3};"
        : "+f"(d[0]), "+f"(d[1]), "+f"(d[2]), "+f"(d[3])
        : "r"(a0), "r"(a1), "r"(a2), "r"(a3), "r"(b0), "r"(b1));
}

// truncation split: hi = f with low 16 bits zeroed, lo = rn(f - hi)
__device__ __forceinline__ void split_st(float f, __nv_bfloat16* ph, __nv_bfloat16* pl) {
    unsigned u = __float_as_uint(f);
    unsigned short hb = (unsigned short)(u >> 16);
    float hf = __uint_as_float(u & 0xFFFF0000u);
    __nv_bfloat16 h; memcpy(&h, &hb, 2);
    *ph = h;
    *pl = __float2bfloat16(f - hf);
}

// ==================== main solve kernel =====================================
// 1 warp = 32 problems. A-hi fragments in registers (loaded once); A-lo in
// block-shared smem. B/F staged per-warp in smem.
__global__ void __launch_bounds__(128, 3) solve_kernel(
    const float* __restrict__ y_init, const float* __restrict__ Bin,
    const float* __restrict__ a, float* __restrict__ out)
{
    __shared__ alignas(16) __nv_bfloat16 sB[4][2][32*BSS];
    __shared__ alignas(16) __nv_bfloat16 sF[4][2][8*FSS];
    __shared__ alignas(16) unsigned sGlo[1024];
    __shared__ alignas(16) unsigned sClo[1024];

    int tid  = threadIdx.x;
    int wid  = tid >> 5;
    int lane = tid & 31;
    int g = lane >> 2, t = lane & 3;

    // copy lo fragment tables to smem
    {
        const uint4* gsrc = (const uint4*)(g_Gfrag + 1024);
        const uint4* csrc = (const uint4*)(g_Cfrag + 1024);
        uint4* gdst = (uint4*)sGlo;
        uint4* cdst = (uint4*)sClo;
        for (int e = tid; e < 256; e += 128) { gdst[e] = gsrc[e]; cdst[e] = csrc[e]; }
    }

    // hi fragments -> registers (loop-invariant)
    uint4 GhR[2][4], ChR[4][2];
    #pragma unroll
    for (int kt = 0; kt < 2; kt++)
        #pragma unroll
        for (int mt = 0; mt < 4; mt++)
            GhR[kt][mt] = __ldg((const uint4*)&g_Gfrag[((kt*4 + mt)*32 + lane)*4]);
    #pragma unroll
    for (int kt = 0; kt < 4; kt++)
        #pragma unroll
        for (int mt = 0; mt < 2; mt++)
            ChR[kt][mt] = __ldg((const uint4*)&g_Cfrag[((kt*2 + mt)*32 + lane)*4]);

    // per-thread row constants (rows g + 8j)
    float sin_r[8], tc1_r[8];
    #pragma unroll
    for (int j = 0; j < 8; j++) {
        sin_r[j] = __ldg(&c_sin[g + 8*j]);
        tc1_r[j] = d_TB.TC1[g + 8*j];
    }
    float V_r[4];
    #pragma unroll
    for (int j = 0; j < 4; j++) V_r[j] = __ldg(&c_V[g + 8*j]);
    float invs = __ldg(&c_scal[0]);
    float sin0 = __ldg(&c_scal[1]);

    // own problem (column = lane)
    int pbase = blockIdx.x * 128 + wid * 32;
    int pcol  = pbase + lane;
    float y0  = y_init[pcol];
    float aj0 = __ldg(&a[pcol & 511]);
    float w0  = (sin0 - fast_tanh(y0 * aj0)) * invs;

    // initial B staging
    {
        const float* bp = Bin + (long)pcol * NB;
        __nv_bfloat16* bh = &sB[wid][0][lane*BSS];
        __nv_bfloat16* bl = &sB[wid][1][lane*BSS];
        #pragma unroll 1
        for (int m = 0; m < NB; m++) split_st(bp[m], &bh[m], &bl[m]);
        __nv_bfloat16 z = __float2bfloat16(0.f);
        bh[30] = z; bh[31] = z; bl[30] = z; bl[31] = z;
    }
    __syncthreads();   // covers lo-table copy too

    #pragma unroll 1
    for (int it = 0; it < NITER; it++) {
        #pragma unroll 1
        for (int nt = 0; nt < 4; nt++) {
            int c0l = nt*8 + 2*t;
            float yn0 = __shfl_sync(0xffffffffu, y0,  c0l);
            float yn1 = __shfl_sync(0xffffffffu, y0,  c0l + 1);
            float wn0 = __shfl_sync(0xffffffffu, w0,  c0l);
            float wn1 = __shfl_sync(0xffffffffu, w0,  c0l + 1);
            float an0 = __shfl_sync(0xffffffffu, aj0, c0l);
            float an1 = __shfl_sync(0xffffffffu, aj0, c0l + 1);

            // ---- GEMM1: Y = G @ B(:, tile nt) ----
            float acc[4][4];
            #pragma unroll
            for (int mt = 0; mt < 4; mt++)
                #pragma unroll
                for (int r = 0; r < 4; r++) acc[mt][r] = 0.f;

            #pragma unroll
            for (int kt = 0; kt < 2; kt++) {
                int boff = (nt*8 + g)*BSS + kt*16 + 2*t;
                unsigned bh0 = *(const unsigned*)&sB[wid][0][boff];
                unsigned bh1 = *(const unsigned*)&sB[wid][0][boff + 8];
                unsigned bl0 = *(const unsigned*)&sB[wid][1][boff];
                unsigned bl1 = *(const unsigned*)&sB[wid][1][boff + 8];
                #pragma unroll
                for (int mt = 0; mt < 4; mt++) {
                    uint4 ah = GhR[kt][mt];
                    uint4 al = *(const uint4*)&sGlo[((kt*4 + mt)*32 + lane)*4];
                    mma_bf16(acc[mt], ah.x, ah.y, ah.z, ah.w, bh0, bh1);
                    mma_bf16(acc[mt], ah.x, ah.y, ah.z, ah.w, bl0, bl1);
                    mma_bf16(acc[mt], al.x, al.y, al.z, al.w, bh0, bh1);
                }
            }

            // ---- elementwise: ya -> f -> split -> F staging ----
            #pragma unroll
            for (int mt = 0; mt < 4; mt++) {
                #pragma unroll
                for (int r = 0; r < 4; r++) {
                    int s = r >> 1, colsel = r & 1;
                    int j = 2*mt + s;
                    float yv = colsel ? yn1 : yn0;
                    float wv = colsel ? wn1 : wn0;
                    float av = colsel ? an1 : an0;
                    float ya = acc[mt][r] + fmaf(wv, tc1_r[j], yv);
                    float f  = sin_r[j] - fast_tanh(ya * av);
                    int cl = 2*t + colsel;
                    int krow = g + 8*j;
                    split_st(f, &sF[wid][0][cl*FSS + krow], &sF[wid][1][cl*FSS + krow]);
                }
            }
            __syncwarp();

            // ---- GEMM2: Bnew = C^T @ F ----
            float acc2[2][4];
            #pragma unroll
            for (int mt = 0; mt < 2; mt++)
                #pragma unroll
                for (int r = 0; r < 4; r++) acc2[mt][r] = 0.f;

            #pragma unroll
            for (int kt = 0; kt < 4; kt++) {
                int foff = g*FSS + kt*16 + 2*t;
                unsigned fh0 = *(const unsigned*)&sF[wid][0][foff];
                unsigned fh1 = *(const unsigned*)&sF[wid][0][foff + 8];
                unsigned fl0 = *(const unsigned*)&sF[wid][1][foff];
                unsigned fl1 = *(const unsigned*)&sF[wid][1][foff + 8];
                #pragma unroll
                for (int mt = 0; mt < 2; mt++) {
                    uint4 ah = ChR[kt][mt];
                    uint4 al = *(const uint4*)&sClo[((kt*2 + mt)*32 + lane)*4];
                    mma_bf16(acc2[mt], ah.x, ah.y, ah.z, ah.w, fh0, fh1);
                    mma_bf16(acc2[mt], ah.x, ah.y, ah.z, ah.w, fl0, fl1);
                    mma_bf16(acc2[mt], al.x, al.y, al.z, al.w, fh0, fh1);
                }
            }
            __syncwarp();

            // ---- B update + staging write ----
            #pragma unroll
            for (int mt = 0; mt < 2; mt++) {
                #pragma unroll
                for (int r = 0; r < 4; r++) {
                    int s = r >> 1, colsel = r & 1;
                    int j2 = 2*mt + s;
                    int m  = g + 8*j2;
                    float wv = colsel ? wn1 : wn0;
                    float Bv = fmaf(invs, acc2[mt][r], -(wv * V_r[j2]));
                    int nabs = nt*8 + 2*t + colsel;
                    split_st(Bv, &sB[wid][0][nabs*BSS + m], &sB[wid][1][nabs*BSS + m]);
                }
            }
            __syncwarp();
        } // nt
    } // it

    // ==================== epilogue (lane = its own column) ==================
    float Bf[NB];
    {
        const __nv_bfloat16* bh = &sB[wid][0][lane*BSS];
        const __nv_bfloat16* bl = &sB[wid][1][lane*BSS];
        #pragma unroll
        for (int m = 0; m < NB; m++)
            Bf[m] = __bfloat162float(bh[m]) + __bfloat162float(bl[m]);
    }

    float h0 = y0 + w0, h1 = w0;
    #pragma unroll
    for (int m = 0; m < NB; m++) {
        h0 = fmaf(-Bf[m], d_TB.P0[m], h0);
        h1 = fmaf(-Bf[m], d_TB.P1[m], h1);
    }

    float* outB = out + 16L*NPROB;
    {
        float* dst = outB + (long)pcol * NCF;
        dst[0] = h0; dst[1] = h1;
        #pragma unroll
        for (int m = 0; m < NB; m++) dst[2+m] = Bf[m];
    }

    #pragma unroll 1
    for (int tt = 0; tt < 16; tt++) {
        float val = fmaf(h0, __ldg(&c_PO[0][tt]), h1 * __ldg(&c_PO[1][tt]));
        #pragma unroll
        for (int m = 0; m < NB; m++)
            val = fmaf(Bf[m], __ldg(&c_PO[m+2][tt]), val);
        out[(long)tt*NPROB + pcol] = val;
    }
}

// ==================== launch ================================================
extern "C" void kernel_launch(void* const* d_in, const int* in_sizes, int n_in,
                              void* d_out, int out_size) {
    const float* y_init = (const float*)d_in[0];
    const float* B_init = (const float*)d_in[1];
    const float* t_span = (const float*)d_in[2];
    const float* a      = (const float*)d_in[3];
    float* out = (float*)d_out;
    setup_kernel<<<1, 256>>>(t_span);
    solve_kernel<<<NPROB/128, 128>>>(y_init, B_init, a, out);
}